// round 1
// baseline (speedup 1.0000x reference)
#include <cuda_runtime.h>
#include <math.h>

// ---------------- problem constants ----------------
#define BQ 2
#define TQ 2048
#define CQ 2048
#define AQ 2048
#define HQ 32
#define HSQ 64
#define MQ (BQ*TQ)          // 4096 tokens
#define DMIX 32
#define DDEC 64
#define NZ (5*DMIX)         // 160
#define EPSG (1e-5f*64.0f)  // GroupNorm eps = 1e-5 * head_size_divisor^2

// ---------------- scratch (device globals; no allocation allowed) ----------------
static __device__ float g_xxx[MQ*CQ];
static __device__ float g_z[MQ*NZ];
static __device__ float g_xw[MQ*CQ];
static __device__ float g_xk[MQ*CQ];
static __device__ float g_xv[MQ*CQ];
static __device__ float g_xr[MQ*CQ];
static __device__ float g_xg[MQ*CQ];
static __device__ float g_r[MQ*AQ];
static __device__ float g_k[MQ*AQ];
static __device__ float g_v[MQ*AQ];
static __device__ float g_g[MQ*AQ];
static __device__ float g_tmpd[MQ*DDEC];
static __device__ float g_w[MQ*AQ];
static __device__ float g_ruk[MQ*HQ];
static __device__ float g_att[MQ*AQ];
static __device__ float g_y[MQ*AQ];

// ---------------- 1) xxx = hidden + (shift(hidden)-hidden)*time_maa_x ----------------
__global__ void prep_xxx_kernel(const float* __restrict__ hidden,
                                const float* __restrict__ maa_x) {
    int i = blockIdx.x * 256 + threadIdx.x;
    if (i >= MQ*CQ) return;
    int c  = i & (CQ-1);
    int bt = i >> 11;                       // / CQ
    float h  = hidden[i];
    float sh = ((bt & (TQ-1)) != 0) ? hidden[i - CQ] : 0.0f;
    g_xxx[i] = h + (sh - h) * maa_x[c];
}

// ---------------- generic tiled SGEMM: C[M,N] = A[M,K] * op(B) ----------------
// BT=true : B is [N,K] row-major (compute A*B^T)   -- used for W_r/W_k/W_v/W_g/W_o
// BT=false: B is [K,N] row-major                   -- used for time_maa_w1, decay_w1
enum { EPI_NONE=0, EPI_TANH=1, EPI_SILU=2 };

template<int EPI, bool BT>
__global__ void __launch_bounds__(256)
sgemm_kernel(const float* __restrict__ A, const float* __restrict__ B,
             float* __restrict__ Cmat, int M, int N, int K) {
    __shared__ float As[8][128];
    __shared__ float Bs[8][128];
    const int tid  = threadIdx.x;
    const int row0 = blockIdx.y * 128;
    const int col0 = blockIdx.x * 128;
    const int tx = tid & 15, ty = tid >> 4;

    float acc[8][8];
#pragma unroll
    for (int i = 0; i < 8; i++)
#pragma unroll
        for (int j = 0; j < 8; j++) acc[i][j] = 0.0f;

    const int lrow = tid >> 1;          // 0..127
    const int lcol = (tid & 1) * 4;     // 0 or 4

    for (int k0 = 0; k0 < K; k0 += 8) {
        // A tile (row-major [M,K], K contiguous) -> transposed stage
        {
            int r = row0 + lrow;
            float4 v = make_float4(0.f,0.f,0.f,0.f);
            if (r < M) v = *(const float4*)(A + (size_t)r*K + k0 + lcol);
            As[lcol+0][lrow] = v.x; As[lcol+1][lrow] = v.y;
            As[lcol+2][lrow] = v.z; As[lcol+3][lrow] = v.w;
        }
        if (BT) {
            int r = col0 + lrow;
            float4 v = make_float4(0.f,0.f,0.f,0.f);
            if (r < N) v = *(const float4*)(B + (size_t)r*K + k0 + lcol);
            Bs[lcol+0][lrow] = v.x; Bs[lcol+1][lrow] = v.y;
            Bs[lcol+2][lrow] = v.z; Bs[lcol+3][lrow] = v.w;
        } else {
            int kr = tid >> 5;              // 0..7
            int nc = (tid & 31) * 4;        // 0..124
#pragma unroll
            for (int j = 0; j < 4; j++) {
                int n = col0 + nc + j;
                Bs[kr][nc+j] = (n < N) ? B[(size_t)(k0+kr)*N + n] : 0.0f;
            }
        }
        __syncthreads();
#pragma unroll
        for (int kk = 0; kk < 8; kk++) {
            float a[8], b[8];
            *(float4*)&a[0] = *(const float4*)&As[kk][ty*8];
            *(float4*)&a[4] = *(const float4*)&As[kk][ty*8+4];
            *(float4*)&b[0] = *(const float4*)&Bs[kk][tx*8];
            *(float4*)&b[4] = *(const float4*)&Bs[kk][tx*8+4];
#pragma unroll
            for (int i = 0; i < 8; i++)
#pragma unroll
                for (int j = 0; j < 8; j++) acc[i][j] = fmaf(a[i], b[j], acc[i][j]);
        }
        __syncthreads();
    }
#pragma unroll
    for (int i = 0; i < 8; i++) {
        int r = row0 + ty*8 + i;
        if (r >= M) continue;
#pragma unroll
        for (int j = 0; j < 8; j++) {
            int c = col0 + tx*8 + j;
            if (c >= N) continue;
            float v = acc[i][j];
            if (EPI == EPI_TANH) v = tanhf(v);
            else if (EPI == EPI_SILU) v = v / (1.0f + expf(-v));
            Cmat[(size_t)r*N + c] = v;
        }
    }
}

// ---------------- 3) mix: xw..xg = hidden + xx*(time_maa_* + z@w2_f) ----------------
// block: 256 threads over c, 8 tokens per block
__global__ void __launch_bounds__(256)
mix_kernel(const float* __restrict__ hidden, const float* __restrict__ w2,
           const float* __restrict__ maa_w, const float* __restrict__ maa_k,
           const float* __restrict__ maa_v, const float* __restrict__ maa_r,
           const float* __restrict__ maa_g) {
    __shared__ float zs[8][NZ];
    const int tid = threadIdx.x;
    const int bt0 = blockIdx.y * 8;
    const int c   = blockIdx.x * 256 + tid;

    for (int idx = tid; idx < 8*NZ; idx += 256)
        zs[idx / NZ][idx % NZ] = g_z[(size_t)(bt0 + idx/NZ)*NZ + (idx % NZ)];
    __syncthreads();

    float acc[5][8];
#pragma unroll
    for (int f = 0; f < 5; f++)
#pragma unroll
        for (int i = 0; i < 8; i++) acc[f][i] = 0.0f;

#pragma unroll
    for (int f = 0; f < 5; f++) {
        for (int d = 0; d < DMIX; d++) {
            float wv = w2[(size_t)(f*DMIX + d)*CQ + c];
#pragma unroll
            for (int i = 0; i < 8; i++) acc[f][i] = fmaf(zs[i][f*DMIX+d], wv, acc[f][i]);
        }
    }
    float mw = maa_w[c], mk = maa_k[c], mv = maa_v[c], mr = maa_r[c], mg = maa_g[c];
#pragma unroll
    for (int i = 0; i < 8; i++) {
        int bt = bt0 + i;
        size_t o = (size_t)bt*CQ + c;
        float h  = hidden[o];
        float sh = ((bt & (TQ-1)) != 0) ? hidden[o - CQ] : 0.0f;
        float xx = sh - h;
        g_xw[o] = h + xx * (mw + acc[0][i]);
        g_xk[o] = h + xx * (mk + acc[1][i]);
        g_xv[o] = h + xx * (mv + acc[2][i]);
        g_xr[o] = h + xx * (mr + acc[3][i]);
        g_xg[o] = h + xx * (mg + acc[4][i]);
    }
}

// ---------------- 6) w = exp(-exp(tmpd@decay_w2 + time_decay)) ----------------
__global__ void __launch_bounds__(256)
decay_final_kernel(const float* __restrict__ w2, const float* __restrict__ tdecay) {
    __shared__ float ts[16][DDEC];
    const int tid = threadIdx.x;
    const int m0  = blockIdx.y * 16;
    const int a   = blockIdx.x * 256 + tid;

    for (int idx = tid; idx < 16*DDEC; idx += 256)
        ts[idx >> 6][idx & 63] = g_tmpd[(size_t)(m0 + (idx >> 6))*DDEC + (idx & 63)];
    __syncthreads();

    float acc[16];
#pragma unroll
    for (int i = 0; i < 16; i++) acc[i] = 0.0f;
    for (int d = 0; d < DDEC; d++) {
        float wv = w2[(size_t)d*AQ + a];
#pragma unroll
        for (int i = 0; i < 16; i++) acc[i] = fmaf(ts[i][d], wv, acc[i]);
    }
    float td = tdecay[a];
#pragma unroll
    for (int i = 0; i < 16; i++)
        g_w[(size_t)(m0+i)*AQ + a] = expf(-expf(acc[i] + td));
}

// ---------------- 7) ruk[b,t,h] = sum_n r*u*k ----------------
__global__ void ruk_kernel(const float* __restrict__ u) {
    int g    = blockIdx.x * 8 + (threadIdx.x >> 5);
    int lane = threadIdx.x & 31;
    int bt = g >> 5;            // / HQ
    int h  = g & 31;
    size_t off = (size_t)bt*AQ + h*HSQ;
    float s = g_r[off+lane]    * u[h*HSQ+lane]    * g_k[off+lane]
            + g_r[off+lane+32] * u[h*HSQ+lane+32] * g_k[off+lane+32];
#pragma unroll
    for (int sh = 16; sh; sh >>= 1) s += __shfl_xor_sync(0xffffffffu, s, sh);
    if (lane == 0) g_ruk[(size_t)bt*HQ + h] = s;
}

// ---------------- 8) WKV sequential scan ----------------
// grid (H, B). 128 threads: m = tid&63 (value dim), half = tid>>6 owns 32 key rows.
__global__ void __launch_bounds__(128)
wkv_kernel() {
    const int h = blockIdx.x, b = blockIdx.y;
    const int tid  = threadIdx.x;
    const int m    = tid & 63;
    const int half = tid >> 6;
    __shared__ float4 s_rkw[64];
    __shared__ float  s_part[128];

    float S[32];
#pragma unroll
    for (int j = 0; j < 32; j++) S[j] = 0.0f;

    const size_t base = (size_t)b*TQ*AQ + (size_t)h*HSQ;
    for (int t = 0; t < TQ; t++) {
        size_t off = base + (size_t)t*AQ;
        if (tid < 64)
            s_rkw[tid] = make_float4(g_r[off+tid], g_k[off+tid], g_w[off+tid], 0.0f);
        float vm   = g_v[off + m];
        float rukt = g_ruk[((size_t)b*TQ + t)*HQ + h];
        __syncthreads();

        float a0 = (half == 0) ? vm * rukt : 0.0f;
        float a1 = 0.0f, a2 = 0.0f, a3 = 0.0f;
        const int nb = half * 32;
#pragma unroll
        for (int j = 0; j < 32; j += 4) {
            float4 q0 = s_rkw[nb+j+0];
            float4 q1 = s_rkw[nb+j+1];
            float4 q2 = s_rkw[nb+j+2];
            float4 q3 = s_rkw[nb+j+3];
            a0 = fmaf(q0.x, S[j+0], a0);  S[j+0] = fmaf(q0.z, S[j+0], q0.y*vm);
            a1 = fmaf(q1.x, S[j+1], a1);  S[j+1] = fmaf(q1.z, S[j+1], q1.y*vm);
            a2 = fmaf(q2.x, S[j+2], a2);  S[j+2] = fmaf(q2.z, S[j+2], q2.y*vm);
            a3 = fmaf(q3.x, S[j+3], a3);  S[j+3] = fmaf(q3.z, S[j+3], q3.y*vm);
        }
        s_part[tid] = (a0 + a1) + (a2 + a3);
        __syncthreads();
        if (half == 0)
            g_att[off + m] = s_part[m] + s_part[m + 64];
    }
}

// ---------------- 9) GroupNorm(per head) * gamma + beta, then * g ----------------
__global__ void gnorm_kernel(const float* __restrict__ gamma, const float* __restrict__ beta) {
    int g    = blockIdx.x * 8 + (threadIdx.x >> 5);
    int lane = threadIdx.x & 31;
    int bt = g >> 5;
    int h  = g & 31;
    size_t off = (size_t)bt*AQ + h*HSQ;
    float x0 = g_att[off+lane], x1 = g_att[off+lane+32];
    float s  = x0 + x1;
    float ss = x0*x0 + x1*x1;
#pragma unroll
    for (int sh = 16; sh; sh >>= 1) {
        s  += __shfl_xor_sync(0xffffffffu, s,  sh);
        ss += __shfl_xor_sync(0xffffffffu, ss, sh);
    }
    float mean = s * (1.0f/64.0f);
    float var  = ss * (1.0f/64.0f) - mean*mean;
    float inv  = rsqrtf(var + EPSG);
    int c0 = h*HSQ + lane, c1 = c0 + 32;
    g_y[off+lane]    = ((x0-mean)*inv*gamma[c0] + beta[c0]) * g_g[off+lane];
    g_y[off+lane+32] = ((x1-mean)*inv*gamma[c1] + beta[c1]) * g_g[off+lane+32];
}

// ---------------- host ----------------
extern "C" void kernel_launch(void* const* d_in, const int* in_sizes, int n_in,
                              void* d_out, int out_size) {
    (void)in_sizes; (void)n_in; (void)out_size;
    const float* hidden  = (const float*)d_in[0];
    const float* maa_x   = (const float*)d_in[1];
    const float* maa_w   = (const float*)d_in[2];
    const float* maa_k   = (const float*)d_in[3];
    const float* maa_v   = (const float*)d_in[4];
    const float* maa_r   = (const float*)d_in[5];
    const float* maa_g   = (const float*)d_in[6];
    const float* maa_w1  = (const float*)d_in[7];
    const float* maa_w2  = (const float*)d_in[8];
    const float* tdecay  = (const float*)d_in[9];
    const float* dec_w1  = (const float*)d_in[10];
    const float* dec_w2  = (const float*)d_in[11];
    const float* u       = (const float*)d_in[12];
    const float* W_r     = (const float*)d_in[13];
    const float* W_k     = (const float*)d_in[14];
    const float* W_v     = (const float*)d_in[15];
    const float* W_g     = (const float*)d_in[16];
    const float* W_o     = (const float*)d_in[17];
    const float* gamma   = (const float*)d_in[18];
    const float* beta    = (const float*)d_in[19];
    float* out = (float*)d_out;

    float *p_xxx, *p_z, *p_xw, *p_xk, *p_xv, *p_xr, *p_xg;
    float *p_r, *p_k, *p_v, *p_g, *p_tmpd, *p_y;
    cudaGetSymbolAddress((void**)&p_xxx,  g_xxx);
    cudaGetSymbolAddress((void**)&p_z,    g_z);
    cudaGetSymbolAddress((void**)&p_xw,   g_xw);
    cudaGetSymbolAddress((void**)&p_xk,   g_xk);
    cudaGetSymbolAddress((void**)&p_xv,   g_xv);
    cudaGetSymbolAddress((void**)&p_xr,   g_xr);
    cudaGetSymbolAddress((void**)&p_xg,   g_xg);
    cudaGetSymbolAddress((void**)&p_r,    g_r);
    cudaGetSymbolAddress((void**)&p_k,    g_k);
    cudaGetSymbolAddress((void**)&p_v,    g_v);
    cudaGetSymbolAddress((void**)&p_g,    g_g);
    cudaGetSymbolAddress((void**)&p_tmpd, g_tmpd);
    cudaGetSymbolAddress((void**)&p_y,    g_y);

    // 1) xxx
    prep_xxx_kernel<<<(MQ*CQ)/256, 256>>>(hidden, maa_x);
    // 2) z = tanh(xxx @ time_maa_w1)   [4096 x 160]
    sgemm_kernel<EPI_TANH, false><<<dim3(2, 32), 256>>>(p_xxx, maa_w1, p_z, MQ, NZ, CQ);
    // 3) mix -> xw,xk,xv,xr,xg
    mix_kernel<<<dim3(CQ/256, MQ/8), 256>>>(hidden, maa_w2, maa_w, maa_k, maa_v, maa_r, maa_g);
    // 4) big NT GEMMs
    sgemm_kernel<EPI_NONE, true><<<dim3(16, 32), 256>>>(p_xr, W_r, p_r, MQ, AQ, CQ);
    sgemm_kernel<EPI_NONE, true><<<dim3(16, 32), 256>>>(p_xk, W_k, p_k, MQ, AQ, CQ);
    sgemm_kernel<EPI_NONE, true><<<dim3(16, 32), 256>>>(p_xv, W_v, p_v, MQ, AQ, CQ);
    sgemm_kernel<EPI_SILU, true><<<dim3(16, 32), 256>>>(p_xg, W_g, p_g, MQ, AQ, CQ);
    // 5) decay low-rank stage 1: tmpd = tanh(xw @ decay_w1)  [4096 x 64]
    sgemm_kernel<EPI_TANH, false><<<dim3(1, 32), 256>>>(p_xw, dec_w1, p_tmpd, MQ, DDEC, CQ);
    // 6) w = exp(-exp(tmpd @ decay_w2 + time_decay))
    decay_final_kernel<<<dim3(AQ/256, MQ/16), 256>>>(dec_w2, tdecay);
    // 7) ruk
    ruk_kernel<<<(MQ*HQ)/8, 256>>>(u);
    // 8) WKV scan
    wkv_kernel<<<dim3(HQ, BQ), 128>>>();
    // 9) GroupNorm + gate
    gnorm_kernel<<<(MQ*HQ)/8, 256>>>(gamma, beta);
    // 10) out = y @ W_o^T
    sgemm_kernel<EPI_NONE, true><<<dim3(16, 32), 256>>>(p_y, W_o, out, MQ, CQ, AQ);
}

// round 2
// speedup vs baseline: 1.6269x; 1.6269x over previous
#include <cuda_runtime.h>
#include <math.h>
#include <stdint.h>

// ---------------- problem constants ----------------
#define BQ 2
#define TQ 2048
#define CQ 2048
#define AQ 2048
#define HQ 32
#define HSQ 64
#define MQ (BQ*TQ)          // 4096 tokens
#define DMIX 32
#define DDEC 64
#define NZ (5*DMIX)         // 160
#define EPSG (1e-5f*64.0f)  // GroupNorm eps = 1e-5 * head_size_divisor^2

// ---------------- scratch (device globals; no allocation allowed) ----------------
static __device__ float g_xxx[MQ*CQ];
static __device__ float g_z[MQ*NZ];
static __device__ float g_xw[MQ*CQ];
static __device__ float g_xk[MQ*CQ];
static __device__ float g_xv[MQ*CQ];
static __device__ float g_xr[MQ*CQ];
static __device__ float g_xg[MQ*CQ];
static __device__ float g_r[MQ*AQ];
static __device__ float g_k[MQ*AQ];
static __device__ float g_v[MQ*AQ];
static __device__ float g_g[MQ*AQ];
static __device__ float g_tmpd[MQ*DDEC];
static __device__ float g_w[MQ*AQ];
static __device__ float g_ruk[MQ*HQ];
static __device__ float g_att[MQ*AQ];
static __device__ float g_y[MQ*AQ];

// ---------------- 1) xxx = hidden + (shift(hidden)-hidden)*time_maa_x ----------------
__global__ void prep_xxx_kernel(const float* __restrict__ hidden,
                                const float* __restrict__ maa_x) {
    int i = blockIdx.x * 256 + threadIdx.x;
    if (i >= MQ*CQ) return;
    int c  = i & (CQ-1);
    int bt = i >> 11;                       // / CQ
    float h  = hidden[i];
    float sh = ((bt & (TQ-1)) != 0) ? hidden[i - CQ] : 0.0f;
    g_xxx[i] = h + (sh - h) * maa_x[c];
}

// ---------------- epilogues ----------------
enum { EPI_NONE=0, EPI_TANH=1, EPI_SILU=2 };
template<int EPI> __device__ __forceinline__ float epi_fn(float v) {
    if (EPI == EPI_TANH) return tanhf(v);
    if (EPI == EPI_SILU) return v / (1.0f + expf(-v));
    return v;
}

// ---------------- tf32 helpers ----------------
__device__ __forceinline__ uint32_t f2tf(float x) {
    uint32_t r;
    asm("cvt.rna.tf32.f32 %0, %1;" : "=r"(r) : "f"(x));
    return r;
}

__device__ __forceinline__ void mma_tf32(float (&d)[4], const uint32_t (&a)[4],
                                         const uint32_t (&b)[2]) {
    asm volatile(
        "mma.sync.aligned.m16n8k8.row.col.f32.tf32.tf32.f32 "
        "{%0,%1,%2,%3}, {%4,%5,%6,%7}, {%8,%9}, {%0,%1,%2,%3};"
        : "+f"(d[0]), "+f"(d[1]), "+f"(d[2]), "+f"(d[3])
        : "r"(a[0]), "r"(a[1]), "r"(a[2]), "r"(a[3]), "r"(b[0]), "r"(b[1]));
}

// ---------------- tensor-core tf32 NT GEMM: C[M,N] = A[M,K] * B[N,K]^T --------------
// Requirements: M%128==0, N%128==0, K%16==0 (holds for all big GEMMs here).
#define AS_STRIDE 20    // 16 + 4 pad  (conflict-free frag loads)
#define BS_STRIDE 136   // 128 + 8 pad (conflict-free frag loads)

template<int EPI>
__global__ void __launch_bounds__(256, 2)
gemm_tf32_nt(const float* __restrict__ A, const float* __restrict__ B,
             float* __restrict__ C, int M, int N, int K) {
    __shared__ uint32_t As[2][128 * AS_STRIDE];
    __shared__ uint32_t Bs[2][16 * BS_STRIDE];

    const int tid  = threadIdx.x;
    const int wid  = tid >> 5, lane = tid & 31;
    const int gq   = lane >> 2, tq = lane & 3;
    const int wm   = (wid & 1) * 64;        // warp row offset in tile
    const int wn   = (wid >> 1) * 32;       // warp col offset in tile
    const int row0 = blockIdx.y * 128;
    const int col0 = blockIdx.x * 128;

    // global staging: each thread carries 2 float4 of A and 2 float4 of B
    const int sr = tid >> 1;                // 0..127 (tile row for A / tile n for B)
    const int sc = (tid & 1) * 8;           // 0 or 8 (k offset)

    const float* Ap = A + (size_t)(row0 + sr) * K + sc;
    const float* Bp = B + (size_t)(col0 + sr) * K + sc;

    float acc[4][4][4];
#pragma unroll
    for (int i = 0; i < 4; i++)
#pragma unroll
        for (int j = 0; j < 4; j++)
#pragma unroll
            for (int q = 0; q < 4; q++) acc[i][j][q] = 0.0f;

    float4 ra0, ra1, rb0, rb1;

    // prologue: load tile 0
    ra0 = *(const float4*)(Ap + 0);
    ra1 = *(const float4*)(Ap + 4);
    rb0 = *(const float4*)(Bp + 0);
    rb1 = *(const float4*)(Bp + 4);
    {
        uint4 pa0 = make_uint4(f2tf(ra0.x), f2tf(ra0.y), f2tf(ra0.z), f2tf(ra0.w));
        uint4 pa1 = make_uint4(f2tf(ra1.x), f2tf(ra1.y), f2tf(ra1.z), f2tf(ra1.w));
        *(uint4*)&As[0][sr * AS_STRIDE + sc]     = pa0;
        *(uint4*)&As[0][sr * AS_STRIDE + sc + 4] = pa1;
        Bs[0][(sc+0)*BS_STRIDE + sr] = f2tf(rb0.x);
        Bs[0][(sc+1)*BS_STRIDE + sr] = f2tf(rb0.y);
        Bs[0][(sc+2)*BS_STRIDE + sr] = f2tf(rb0.z);
        Bs[0][(sc+3)*BS_STRIDE + sr] = f2tf(rb0.w);
        Bs[0][(sc+4)*BS_STRIDE + sr] = f2tf(rb1.x);
        Bs[0][(sc+5)*BS_STRIDE + sr] = f2tf(rb1.y);
        Bs[0][(sc+6)*BS_STRIDE + sr] = f2tf(rb1.z);
        Bs[0][(sc+7)*BS_STRIDE + sr] = f2tf(rb1.w);
    }
    __syncthreads();

    const int NT = K >> 4;   // K/16
    for (int kt = 0; kt < NT; kt++) {
        const int cur = kt & 1;
        if (kt + 1 < NT) {
            const float* ap = Ap + (size_t)(kt + 1) * 16;
            const float* bp = Bp + (size_t)(kt + 1) * 16;
            ra0 = *(const float4*)(ap + 0);
            ra1 = *(const float4*)(ap + 4);
            rb0 = *(const float4*)(bp + 0);
            rb1 = *(const float4*)(bp + 4);
        }
        // compute 2 k-steps of 8
#pragma unroll
        for (int kk = 0; kk < 16; kk += 8) {
            uint32_t af[4][4];
            uint32_t bf[4][2];
#pragma unroll
            for (int im = 0; im < 4; im++) {
                const int r = wm + im * 16;
                const uint32_t* b0 = &As[cur][(r + gq)     * AS_STRIDE + kk + tq];
                const uint32_t* b1 = &As[cur][(r + gq + 8) * AS_STRIDE + kk + tq];
                af[im][0] = b0[0];
                af[im][1] = b1[0];
                af[im][2] = b0[4];
                af[im][3] = b1[4];
            }
#pragma unroll
            for (int jn = 0; jn < 4; jn++) {
                const int c = wn + jn * 8 + gq;
                bf[jn][0] = Bs[cur][(kk + tq)     * BS_STRIDE + c];
                bf[jn][1] = Bs[cur][(kk + tq + 4) * BS_STRIDE + c];
            }
#pragma unroll
            for (int im = 0; im < 4; im++)
#pragma unroll
                for (int jn = 0; jn < 4; jn++)
                    mma_tf32(acc[im][jn], af[im], bf[jn]);
        }
        if (kt + 1 < NT) {
            const int nxt = cur ^ 1;
            uint4 pa0 = make_uint4(f2tf(ra0.x), f2tf(ra0.y), f2tf(ra0.z), f2tf(ra0.w));
            uint4 pa1 = make_uint4(f2tf(ra1.x), f2tf(ra1.y), f2tf(ra1.z), f2tf(ra1.w));
            *(uint4*)&As[nxt][sr * AS_STRIDE + sc]     = pa0;
            *(uint4*)&As[nxt][sr * AS_STRIDE + sc + 4] = pa1;
            Bs[nxt][(sc+0)*BS_STRIDE + sr] = f2tf(rb0.x);
            Bs[nxt][(sc+1)*BS_STRIDE + sr] = f2tf(rb0.y);
            Bs[nxt][(sc+2)*BS_STRIDE + sr] = f2tf(rb0.z);
            Bs[nxt][(sc+3)*BS_STRIDE + sr] = f2tf(rb0.w);
            Bs[nxt][(sc+4)*BS_STRIDE + sr] = f2tf(rb1.x);
            Bs[nxt][(sc+5)*BS_STRIDE + sr] = f2tf(rb1.y);
            Bs[nxt][(sc+6)*BS_STRIDE + sr] = f2tf(rb1.z);
            Bs[nxt][(sc+7)*BS_STRIDE + sr] = f2tf(rb1.w);
        }
        __syncthreads();
    }

    // epilogue
#pragma unroll
    for (int im = 0; im < 4; im++) {
        const int r = row0 + wm + im * 16 + gq;
#pragma unroll
        for (int jn = 0; jn < 4; jn++) {
            const int c = col0 + wn + jn * 8 + 2 * tq;
            float2 v0 = make_float2(epi_fn<EPI>(acc[im][jn][0]), epi_fn<EPI>(acc[im][jn][1]));
            float2 v1 = make_float2(epi_fn<EPI>(acc[im][jn][2]), epi_fn<EPI>(acc[im][jn][3]));
            *(float2*)&C[(size_t)r * N + c]       = v0;
            *(float2*)&C[(size_t)(r + 8) * N + c] = v1;
        }
    }
}

// ---------------- small SIMT SGEMM (kept fp32-exact for the decay chain + z) ---------
// BT=false: B is [K,N] row-major
template<int EPI, bool BT>
__global__ void __launch_bounds__(256)
sgemm_kernel(const float* __restrict__ A, const float* __restrict__ B,
             float* __restrict__ Cmat, int M, int N, int K) {
    __shared__ float As[8][128];
    __shared__ float Bs[8][128];
    const int tid  = threadIdx.x;
    const int row0 = blockIdx.y * 128;
    const int col0 = blockIdx.x * 128;
    const int tx = tid & 15, ty = tid >> 4;

    float acc[8][8];
#pragma unroll
    for (int i = 0; i < 8; i++)
#pragma unroll
        for (int j = 0; j < 8; j++) acc[i][j] = 0.0f;

    const int lrow = tid >> 1;
    const int lcol = (tid & 1) * 4;

    for (int k0 = 0; k0 < K; k0 += 8) {
        {
            int r = row0 + lrow;
            float4 v = make_float4(0.f,0.f,0.f,0.f);
            if (r < M) v = *(const float4*)(A + (size_t)r*K + k0 + lcol);
            As[lcol+0][lrow] = v.x; As[lcol+1][lrow] = v.y;
            As[lcol+2][lrow] = v.z; As[lcol+3][lrow] = v.w;
        }
        if (BT) {
            int r = col0 + lrow;
            float4 v = make_float4(0.f,0.f,0.f,0.f);
            if (r < N) v = *(const float4*)(B + (size_t)r*K + k0 + lcol);
            Bs[lcol+0][lrow] = v.x; Bs[lcol+1][lrow] = v.y;
            Bs[lcol+2][lrow] = v.z; Bs[lcol+3][lrow] = v.w;
        } else {
            int kr = tid >> 5;
            int nc = (tid & 31) * 4;
#pragma unroll
            for (int j = 0; j < 4; j++) {
                int n = col0 + nc + j;
                Bs[kr][nc+j] = (n < N) ? B[(size_t)(k0+kr)*N + n] : 0.0f;
            }
        }
        __syncthreads();
#pragma unroll
        for (int kk = 0; kk < 8; kk++) {
            float a[8], b[8];
            *(float4*)&a[0] = *(const float4*)&As[kk][ty*8];
            *(float4*)&a[4] = *(const float4*)&As[kk][ty*8+4];
            *(float4*)&b[0] = *(const float4*)&Bs[kk][tx*8];
            *(float4*)&b[4] = *(const float4*)&Bs[kk][tx*8+4];
#pragma unroll
            for (int i = 0; i < 8; i++)
#pragma unroll
                for (int j = 0; j < 8; j++) acc[i][j] = fmaf(a[i], b[j], acc[i][j]);
        }
        __syncthreads();
    }
#pragma unroll
    for (int i = 0; i < 8; i++) {
        int r = row0 + ty*8 + i;
        if (r >= M) continue;
#pragma unroll
        for (int j = 0; j < 8; j++) {
            int c = col0 + tx*8 + j;
            if (c >= N) continue;
            Cmat[(size_t)r*N + c] = epi_fn<EPI>(acc[i][j]);
        }
    }
}

// ---------------- 3) mix: xw..xg = hidden + xx*(time_maa_* + z@w2_f) ----------------
__global__ void __launch_bounds__(256)
mix_kernel(const float* __restrict__ hidden, const float* __restrict__ w2,
           const float* __restrict__ maa_w, const float* __restrict__ maa_k,
           const float* __restrict__ maa_v, const float* __restrict__ maa_r,
           const float* __restrict__ maa_g) {
    __shared__ float zs[8][NZ];
    const int tid = threadIdx.x;
    const int bt0 = blockIdx.y * 8;
    const int c   = blockIdx.x * 256 + tid;

    for (int idx = tid; idx < 8*NZ; idx += 256)
        zs[idx / NZ][idx % NZ] = g_z[(size_t)(bt0 + idx/NZ)*NZ + (idx % NZ)];
    __syncthreads();

    float acc[5][8];
#pragma unroll
    for (int f = 0; f < 5; f++)
#pragma unroll
        for (int i = 0; i < 8; i++) acc[f][i] = 0.0f;

#pragma unroll
    for (int f = 0; f < 5; f++) {
        for (int d = 0; d < DMIX; d++) {
            float wv = w2[(size_t)(f*DMIX + d)*CQ + c];
#pragma unroll
            for (int i = 0; i < 8; i++) acc[f][i] = fmaf(zs[i][f*DMIX+d], wv, acc[f][i]);
        }
    }
    float mw = maa_w[c], mk = maa_k[c], mv = maa_v[c], mr = maa_r[c], mg = maa_g[c];
#pragma unroll
    for (int i = 0; i < 8; i++) {
        int bt = bt0 + i;
        size_t o = (size_t)bt*CQ + c;
        float h  = hidden[o];
        float sh = ((bt & (TQ-1)) != 0) ? hidden[o - CQ] : 0.0f;
        float xx = sh - h;
        g_xw[o] = h + xx * (mw + acc[0][i]);
        g_xk[o] = h + xx * (mk + acc[1][i]);
        g_xv[o] = h + xx * (mv + acc[2][i]);
        g_xr[o] = h + xx * (mr + acc[3][i]);
        g_xg[o] = h + xx * (mg + acc[4][i]);
    }
}

// ---------------- 6) w = exp(-exp(tmpd@decay_w2 + time_decay)) ----------------
__global__ void __launch_bounds__(256)
decay_final_kernel(const float* __restrict__ w2, const float* __restrict__ tdecay) {
    __shared__ float ts[16][DDEC];
    const int tid = threadIdx.x;
    const int m0  = blockIdx.y * 16;
    const int a   = blockIdx.x * 256 + tid;

    for (int idx = tid; idx < 16*DDEC; idx += 256)
        ts[idx >> 6][idx & 63] = g_tmpd[(size_t)(m0 + (idx >> 6))*DDEC + (idx & 63)];
    __syncthreads();

    float acc[16];
#pragma unroll
    for (int i = 0; i < 16; i++) acc[i] = 0.0f;
    for (int d = 0; d < DDEC; d++) {
        float wv = w2[(size_t)d*AQ + a];
#pragma unroll
        for (int i = 0; i < 16; i++) acc[i] = fmaf(ts[i][d], wv, acc[i]);
    }
    float td = tdecay[a];
#pragma unroll
    for (int i = 0; i < 16; i++)
        g_w[(size_t)(m0+i)*AQ + a] = expf(-expf(acc[i] + td));
}

// ---------------- 7) ruk[b,t,h] = sum_n r*u*k ----------------
__global__ void ruk_kernel(const float* __restrict__ u) {
    int g    = blockIdx.x * 8 + (threadIdx.x >> 5);
    int lane = threadIdx.x & 31;
    int bt = g >> 5;
    int h  = g & 31;
    size_t off = (size_t)bt*AQ + h*HSQ;
    float s = g_r[off+lane]    * u[h*HSQ+lane]    * g_k[off+lane]
            + g_r[off+lane+32] * u[h*HSQ+lane+32] * g_k[off+lane+32];
#pragma unroll
    for (int sh = 16; sh; sh >>= 1) s += __shfl_xor_sync(0xffffffffu, s, sh);
    if (lane == 0) g_ruk[(size_t)bt*HQ + h] = s;
}

// ---------------- 8) WKV sequential scan ----------------
__global__ void __launch_bounds__(128)
wkv_kernel() {
    const int h = blockIdx.x, b = blockIdx.y;
    const int tid  = threadIdx.x;
    const int m    = tid & 63;
    const int half = tid >> 6;
    __shared__ float4 s_rkw[64];
    __shared__ float  s_part[128];

    float S[32];
#pragma unroll
    for (int j = 0; j < 32; j++) S[j] = 0.0f;

    const size_t base = (size_t)b*TQ*AQ + (size_t)h*HSQ;
    for (int t = 0; t < TQ; t++) {
        size_t off = base + (size_t)t*AQ;
        if (tid < 64)
            s_rkw[tid] = make_float4(g_r[off+tid], g_k[off+tid], g_w[off+tid], 0.0f);
        float vm   = g_v[off + m];
        float rukt = g_ruk[((size_t)b*TQ + t)*HQ + h];
        __syncthreads();

        float a0 = (half == 0) ? vm * rukt : 0.0f;
        float a1 = 0.0f, a2 = 0.0f, a3 = 0.0f;
        const int nb = half * 32;
#pragma unroll
        for (int j = 0; j < 32; j += 4) {
            float4 q0 = s_rkw[nb+j+0];
            float4 q1 = s_rkw[nb+j+1];
            float4 q2 = s_rkw[nb+j+2];
            float4 q3 = s_rkw[nb+j+3];
            a0 = fmaf(q0.x, S[j+0], a0);  S[j+0] = fmaf(q0.z, S[j+0], q0.y*vm);
            a1 = fmaf(q1.x, S[j+1], a1);  S[j+1] = fmaf(q1.z, S[j+1], q1.y*vm);
            a2 = fmaf(q2.x, S[j+2], a2);  S[j+2] = fmaf(q2.z, S[j+2], q2.y*vm);
            a3 = fmaf(q3.x, S[j+3], a3);  S[j+3] = fmaf(q3.z, S[j+3], q3.y*vm);
        }
        s_part[tid] = (a0 + a1) + (a2 + a3);
        __syncthreads();
        if (half == 0)
            g_att[off + m] = s_part[m] + s_part[m + 64];
    }
}

// ---------------- 9) GroupNorm(per head) * gamma + beta, then * g ----------------
__global__ void gnorm_kernel(const float* __restrict__ gamma, const float* __restrict__ beta) {
    int g    = blockIdx.x * 8 + (threadIdx.x >> 5);
    int lane = threadIdx.x & 31;
    int bt = g >> 5;
    int h  = g & 31;
    size_t off = (size_t)bt*AQ + h*HSQ;
    float x0 = g_att[off+lane], x1 = g_att[off+lane+32];
    float s  = x0 + x1;
    float ss = x0*x0 + x1*x1;
#pragma unroll
    for (int sh = 16; sh; sh >>= 1) {
        s  += __shfl_xor_sync(0xffffffffu, s,  sh);
        ss += __shfl_xor_sync(0xffffffffu, ss, sh);
    }
    float mean = s * (1.0f/64.0f);
    float var  = ss * (1.0f/64.0f) - mean*mean;
    float inv  = rsqrtf(var + EPSG);
    int c0 = h*HSQ + lane, c1 = c0 + 32;
    g_y[off+lane]    = ((x0-mean)*inv*gamma[c0] + beta[c0]) * g_g[off+lane];
    g_y[off+lane+32] = ((x1-mean)*inv*gamma[c1] + beta[c1]) * g_g[off+lane+32];
}

// ---------------- host ----------------
extern "C" void kernel_launch(void* const* d_in, const int* in_sizes, int n_in,
                              void* d_out, int out_size) {
    (void)in_sizes; (void)n_in; (void)out_size;
    const float* hidden  = (const float*)d_in[0];
    const float* maa_x   = (const float*)d_in[1];
    const float* maa_w   = (const float*)d_in[2];
    const float* maa_k   = (const float*)d_in[3];
    const float* maa_v   = (const float*)d_in[4];
    const float* maa_r   = (const float*)d_in[5];
    const float* maa_g   = (const float*)d_in[6];
    const float* maa_w1  = (const float*)d_in[7];
    const float* maa_w2  = (const float*)d_in[8];
    const float* tdecay  = (const float*)d_in[9];
    const float* dec_w1  = (const float*)d_in[10];
    const float* dec_w2  = (const float*)d_in[11];
    const float* u       = (const float*)d_in[12];
    const float* W_r     = (const float*)d_in[13];
    const float* W_k     = (const float*)d_in[14];
    const float* W_v     = (const float*)d_in[15];
    const float* W_g     = (const float*)d_in[16];
    const float* W_o     = (const float*)d_in[17];
    const float* gamma   = (const float*)d_in[18];
    const float* beta    = (const float*)d_in[19];
    float* out = (float*)d_out;

    float *p_xxx, *p_z, *p_xw, *p_xk, *p_xv, *p_xr, *p_xg;
    float *p_r, *p_k, *p_v, *p_g, *p_tmpd, *p_y;
    cudaGetSymbolAddress((void**)&p_xxx,  g_xxx);
    cudaGetSymbolAddress((void**)&p_z,    g_z);
    cudaGetSymbolAddress((void**)&p_xw,   g_xw);
    cudaGetSymbolAddress((void**)&p_xk,   g_xk);
    cudaGetSymbolAddress((void**)&p_xv,   g_xv);
    cudaGetSymbolAddress((void**)&p_xr,   g_xr);
    cudaGetSymbolAddress((void**)&p_xg,   g_xg);
    cudaGetSymbolAddress((void**)&p_r,    g_r);
    cudaGetSymbolAddress((void**)&p_k,    g_k);
    cudaGetSymbolAddress((void**)&p_v,    g_v);
    cudaGetSymbolAddress((void**)&p_g,    g_g);
    cudaGetSymbolAddress((void**)&p_tmpd, g_tmpd);
    cudaGetSymbolAddress((void**)&p_y,    g_y);

    // 1) xxx
    prep_xxx_kernel<<<(MQ*CQ)/256, 256>>>(hidden, maa_x);
    // 2) z = tanh(xxx @ time_maa_w1)   [4096 x 160]  (fp32 exact, small)
    sgemm_kernel<EPI_TANH, false><<<dim3(2, 32), 256>>>(p_xxx, maa_w1, p_z, MQ, NZ, CQ);
    // 3) mix -> xw,xk,xv,xr,xg
    mix_kernel<<<dim3(CQ/256, MQ/8), 256>>>(hidden, maa_w2, maa_w, maa_k, maa_v, maa_r, maa_g);
    // 4) big NT GEMMs on tensor cores (tf32)
    gemm_tf32_nt<EPI_NONE><<<dim3(AQ/128, MQ/128), 256>>>(p_xr, W_r, p_r, MQ, AQ, CQ);
    gemm_tf32_nt<EPI_NONE><<<dim3(AQ/128, MQ/128), 256>>>(p_xk, W_k, p_k, MQ, AQ, CQ);
    gemm_tf32_nt<EPI_NONE><<<dim3(AQ/128, MQ/128), 256>>>(p_xv, W_v, p_v, MQ, AQ, CQ);
    gemm_tf32_nt<EPI_SILU><<<dim3(AQ/128, MQ/128), 256>>>(p_xg, W_g, p_g, MQ, AQ, CQ);
    // 5) decay low-rank stage 1 (fp32 exact — error-compounding path)
    sgemm_kernel<EPI_TANH, false><<<dim3(1, 32), 256>>>(p_xw, dec_w1, p_tmpd, MQ, DDEC, CQ);
    // 6) w = exp(-exp(tmpd @ decay_w2 + time_decay))
    decay_final_kernel<<<dim3(AQ/256, MQ/16), 256>>>(dec_w2, tdecay);
    // 7) ruk
    ruk_kernel<<<(MQ*HQ)/8, 256>>>(u);
    // 8) WKV scan
    wkv_kernel<<<dim3(HQ, BQ), 128>>>();
    // 9) GroupNorm + gate
    gnorm_kernel<<<(MQ*HQ)/8, 256>>>(gamma, beta);
    // 10) out = y @ W_o^T (tensor cores)
    gemm_tf32_nt<EPI_NONE><<<dim3(CQ/128, MQ/128), 256>>>(p_y, W_o, out, MQ, CQ, AQ);
}

// round 5
// speedup vs baseline: 1.6888x; 1.0381x over previous
#include <cuda_runtime.h>
#include <cuda_bf16.h>
#include <math.h>
#include <stdint.h>

// ---------------- problem constants ----------------
#define BQ 2
#define TQ 2048
#define CQ 2048
#define AQ 2048
#define HQ 32
#define HSQ 64
#define MQ (BQ*TQ)          // 4096 tokens
#define DMIX 32
#define DDEC 64
#define NZ (5*DMIX)         // 160
#define NSLAB 8
#define EPSG (1e-5f*64.0f)  // GroupNorm eps = 1e-5 * head_size_divisor^2

// ---------------- scratch (device globals; no allocation allowed) ----------------
static __device__ float g_xxx[MQ*CQ];
static __device__ float g_zp[NSLAB*MQ*NZ];     // split-K partials for z
static __device__ float g_z[MQ*NZ];
static __device__ float g_xw[MQ*CQ];
static __device__ float g_xk[MQ*CQ];
static __device__ float g_xv[MQ*CQ];
static __device__ float g_xr[MQ*CQ];
static __device__ float g_xg[MQ*CQ];
static __device__ float g_r[MQ*AQ];
static __device__ float g_k[MQ*AQ];
static __device__ float g_v[MQ*AQ];
static __device__ float g_g[MQ*AQ];
static __device__ float g_tp[NSLAB*MQ*DDEC];   // split-K partials for tmpd
static __device__ float g_tmpd[MQ*DDEC];
static __device__ float g_w[MQ*AQ];
static __device__ float g_ruk[MQ*HQ];
static __device__ float g_att[MQ*AQ];
static __device__ float g_y[MQ*AQ];

// ---------------- 1) xxx = hidden + (shift(hidden)-hidden)*time_maa_x ----------------
__global__ void prep_xxx_kernel(const float* __restrict__ hidden,
                                const float* __restrict__ maa_x) {
    int i = blockIdx.x * 256 + threadIdx.x;
    if (i >= MQ*CQ) return;
    int c  = i & (CQ-1);
    int bt = i >> 11;
    float h  = hidden[i];
    float sh = ((bt & (TQ-1)) != 0) ? hidden[i - CQ] : 0.0f;
    g_xxx[i] = h + (sh - h) * maa_x[c];
}

// ---------------- epilogues ----------------
enum { EPI_NONE=0, EPI_TANH=1, EPI_SILU=2 };
template<int EPI> __device__ __forceinline__ float epi_fn(float v) {
    if (EPI == EPI_TANH) return tanhf(v);
    if (EPI == EPI_SILU) return v / (1.0f + expf(-v));
    return v;
}

// ---------------- bf16 split helpers ----------------
// pack two consecutive-k floats into bf16x2 hi + bf16x2 lo (residual)
__device__ __forceinline__ void cvt_pair(float x, float y, uint32_t& hi, uint32_t& lo) {
    __nv_bfloat162 h = __floats2bfloat162_rn(x, y);   // .x = x (low half)
    float rx = x - __bfloat162float(h.x);
    float ry = y - __bfloat162float(h.y);
    __nv_bfloat162 l = __floats2bfloat162_rn(rx, ry);
    hi = *(uint32_t*)&h;
    lo = *(uint32_t*)&l;
}

__device__ __forceinline__ void mma_bf16(float (&d)[4], const uint32_t (&a)[4],
                                         const uint32_t (&b)[2]) {
    asm volatile(
        "mma.sync.aligned.m16n8k16.row.col.f32.bf16.bf16.f32 "
        "{%0,%1,%2,%3}, {%4,%5,%6,%7}, {%8,%9}, {%0,%1,%2,%3};"
        : "+f"(d[0]), "+f"(d[1]), "+f"(d[2]), "+f"(d[3])
        : "r"(a[0]), "r"(a[1]), "r"(a[2]), "r"(a[3]), "r"(b[0]), "r"(b[1]));
}

// ---------------- bf16 3-term NT GEMM: C[M,N] = A[M,K] * B[N,K]^T --------------
// error per element ~2^-18 (hi*hi + hi*lo + lo*hi). M,N % 128 == 0, K % 16 == 0.
#define XSTRIDE 12   // 8 k-pairs + 4 pad words (frag loads conflict-free mod 32)

template<int EPI>
__global__ void __launch_bounds__(256, 2)
gemm_bf16_nt(const float* __restrict__ A, const float* __restrict__ B,
             float* __restrict__ C, int M, int N, int K) {
    __shared__ uint32_t AsH[2][128*XSTRIDE];
    __shared__ uint32_t AsL[2][128*XSTRIDE];
    __shared__ uint32_t BsH[2][128*XSTRIDE];
    __shared__ uint32_t BsL[2][128*XSTRIDE];

    const int tid  = threadIdx.x;
    const int wid  = tid >> 5, lane = tid & 31;
    const int gq   = lane >> 2, tq = lane & 3;
    const int wm   = (wid & 1) * 64;
    const int wn   = (wid >> 1) * 32;
    const int row0 = blockIdx.y * 128;
    const int col0 = blockIdx.x * 128;

    // staging: each thread handles one row (sr) and 8 consecutive k (sc)
    const int sr = tid >> 1;
    const int sc = (tid & 1) * 8;     // k offset
    const int sp = sc >> 1;           // pair offset (0 or 4)

    const float* Ap = A + (size_t)(row0 + sr) * K + sc;
    const float* Bp = B + (size_t)(col0 + sr) * K + sc;

    float acc[4][4][4];
#pragma unroll
    for (int i = 0; i < 4; i++)
#pragma unroll
        for (int j = 0; j < 4; j++)
#pragma unroll
            for (int q = 0; q < 4; q++) acc[i][j][q] = 0.0f;

    float4 ra0, ra1, rb0, rb1;

    // prologue: stage tile 0
    ra0 = *(const float4*)(Ap + 0);
    ra1 = *(const float4*)(Ap + 4);
    rb0 = *(const float4*)(Bp + 0);
    rb1 = *(const float4*)(Bp + 4);
    {
        uint4 h, l;
        cvt_pair(ra0.x, ra0.y, h.x, l.x); cvt_pair(ra0.z, ra0.w, h.y, l.y);
        cvt_pair(ra1.x, ra1.y, h.z, l.z); cvt_pair(ra1.z, ra1.w, h.w, l.w);
        *(uint4*)&AsH[0][sr*XSTRIDE + sp] = h;
        *(uint4*)&AsL[0][sr*XSTRIDE + sp] = l;
        cvt_pair(rb0.x, rb0.y, h.x, l.x); cvt_pair(rb0.z, rb0.w, h.y, l.y);
        cvt_pair(rb1.x, rb1.y, h.z, l.z); cvt_pair(rb1.z, rb1.w, h.w, l.w);
        *(uint4*)&BsH[0][sr*XSTRIDE + sp] = h;
        *(uint4*)&BsL[0][sr*XSTRIDE + sp] = l;
    }
    __syncthreads();

    const int NT = K >> 4;
    for (int kt = 0; kt < NT; kt++) {
        const int cur = kt & 1;
        if (kt + 1 < NT) {
            const float* ap = Ap + (size_t)(kt + 1) * 16;
            const float* bp = Bp + (size_t)(kt + 1) * 16;
            ra0 = *(const float4*)(ap + 0);
            ra1 = *(const float4*)(ap + 4);
            rb0 = *(const float4*)(bp + 0);
            rb1 = *(const float4*)(bp + 4);
        }
        // preload B frags for all 4 jn
        uint32_t bH[4][2], bL[4][2];
#pragma unroll
        for (int jn = 0; jn < 4; jn++) {
            const int c = (wn + jn*8 + gq) * XSTRIDE;
            bH[jn][0] = BsH[cur][c + tq];
            bH[jn][1] = BsH[cur][c + tq + 4];
            bL[jn][0] = BsL[cur][c + tq];
            bL[jn][1] = BsL[cur][c + tq + 4];
        }
#pragma unroll
        for (int im = 0; im < 4; im++) {
            const int r0i = (wm + im*16 + gq) * XSTRIDE;
            const int r1i = r0i + 8*XSTRIDE;
            uint32_t aH[4], aL[4];
            aH[0] = AsH[cur][r0i + tq];     aH[1] = AsH[cur][r1i + tq];
            aH[2] = AsH[cur][r0i + tq + 4]; aH[3] = AsH[cur][r1i + tq + 4];
            aL[0] = AsL[cur][r0i + tq];     aL[1] = AsL[cur][r1i + tq];
            aL[2] = AsL[cur][r0i + tq + 4]; aL[3] = AsL[cur][r1i + tq + 4];
#pragma unroll
            for (int jn = 0; jn < 4; jn++) {
                mma_bf16(acc[im][jn], aH, bH[jn]);
                mma_bf16(acc[im][jn], aH, bL[jn]);
                mma_bf16(acc[im][jn], aL, bH[jn]);
            }
        }
        if (kt + 1 < NT) {
            const int nxt = cur ^ 1;
            uint4 h, l;
            cvt_pair(ra0.x, ra0.y, h.x, l.x); cvt_pair(ra0.z, ra0.w, h.y, l.y);
            cvt_pair(ra1.x, ra1.y, h.z, l.z); cvt_pair(ra1.z, ra1.w, h.w, l.w);
            *(uint4*)&AsH[nxt][sr*XSTRIDE + sp] = h;
            *(uint4*)&AsL[nxt][sr*XSTRIDE + sp] = l;
            cvt_pair(rb0.x, rb0.y, h.x, l.x); cvt_pair(rb0.z, rb0.w, h.y, l.y);
            cvt_pair(rb1.x, rb1.y, h.z, l.z); cvt_pair(rb1.z, rb1.w, h.w, l.w);
            *(uint4*)&BsH[nxt][sr*XSTRIDE + sp] = h;
            *(uint4*)&BsL[nxt][sr*XSTRIDE + sp] = l;
        }
        __syncthreads();
    }

    // epilogue (m16n8 C layout: c0,c1 at row gq, cols 2tq..; c2,c3 at row gq+8)
#pragma unroll
    for (int im = 0; im < 4; im++) {
        const int r = row0 + wm + im*16 + gq;
#pragma unroll
        for (int jn = 0; jn < 4; jn++) {
            const int c = col0 + wn + jn*8 + 2*tq;
            float2 v0 = make_float2(epi_fn<EPI>(acc[im][jn][0]), epi_fn<EPI>(acc[im][jn][1]));
            float2 v1 = make_float2(epi_fn<EPI>(acc[im][jn][2]), epi_fn<EPI>(acc[im][jn][3]));
            *(float2*)&C[(size_t)r * N + c]       = v0;
            *(float2*)&C[(size_t)(r + 8) * N + c] = v1;
        }
    }
}

// ---------------- small SIMT SGEMM, split-K slabs: P[z] = A[:,kz] * B[kz,:] --------
// B is [K,N] row-major. blockIdx.z selects the K slab. Output to P + z*M*N.
__global__ void __launch_bounds__(256)
sgemm_splitk_kernel(const float* __restrict__ A, const float* __restrict__ B,
                    float* __restrict__ P, int M, int N, int K) {
    const int kslab = K / NSLAB;
    const int k0 = blockIdx.z * kslab;
    float* Cmat = P + (size_t)blockIdx.z * M * N;

    __shared__ float As[8][128];
    __shared__ float Bs[8][128];
    const int tid  = threadIdx.x;
    const int row0 = blockIdx.y * 128;
    const int col0 = blockIdx.x * 128;
    const int tx = tid & 15, ty = tid >> 4;

    float acc[8][8];
#pragma unroll
    for (int i = 0; i < 8; i++)
#pragma unroll
        for (int j = 0; j < 8; j++) acc[i][j] = 0.0f;

    const int lrow = tid >> 1;
    const int lcol = (tid & 1) * 4;

    for (int kk0 = k0; kk0 < k0 + kslab; kk0 += 8) {
        {
            int r = row0 + lrow;
            float4 v = make_float4(0.f,0.f,0.f,0.f);
            if (r < M) v = *(const float4*)(A + (size_t)r*K + kk0 + lcol);
            As[lcol+0][lrow] = v.x; As[lcol+1][lrow] = v.y;
            As[lcol+2][lrow] = v.z; As[lcol+3][lrow] = v.w;
        }
        {
            int kr = tid >> 5;
            int nc = (tid & 31) * 4;
#pragma unroll
            for (int j = 0; j < 4; j++) {
                int n = col0 + nc + j;
                Bs[kr][nc+j] = (n < N) ? B[(size_t)(kk0+kr)*N + n] : 0.0f;
            }
        }
        __syncthreads();
#pragma unroll
        for (int kk = 0; kk < 8; kk++) {
            float a[8], b[8];
            *(float4*)&a[0] = *(const float4*)&As[kk][ty*8];
            *(float4*)&a[4] = *(const float4*)&As[kk][ty*8+4];
            *(float4*)&b[0] = *(const float4*)&Bs[kk][tx*8];
            *(float4*)&b[4] = *(const float4*)&Bs[kk][tx*8+4];
#pragma unroll
            for (int i = 0; i < 8; i++)
#pragma unroll
                for (int j = 0; j < 8; j++) acc[i][j] = fmaf(a[i], b[j], acc[i][j]);
        }
        __syncthreads();
    }
#pragma unroll
    for (int i = 0; i < 8; i++) {
        int r = row0 + ty*8 + i;
        if (r >= M) continue;
#pragma unroll
        for (int j = 0; j < 8; j++) {
            int c = col0 + tx*8 + j;
            if (c >= N) continue;
            Cmat[(size_t)r*N + c] = acc[i][j];
        }
    }
}

// sum 8 slabs in fixed order, apply tanh
__global__ void reduce8_tanh_kernel(const float* __restrict__ P, float* __restrict__ o,
                                    int MN) {
    int i = blockIdx.x * 256 + threadIdx.x;
    if (i >= MN) return;
    float s = 0.0f;
#pragma unroll
    for (int z = 0; z < NSLAB; z++) s += P[(size_t)z*MN + i];
    o[i] = tanhf(s);
}

// ---------------- 3) mix: xw..xg = hidden + xx*(time_maa_* + z@w2_f) ----------------
__global__ void __launch_bounds__(256)
mix_kernel(const float* __restrict__ hidden, const float* __restrict__ w2,
           const float* __restrict__ maa_w, const float* __restrict__ maa_k,
           const float* __restrict__ maa_v, const float* __restrict__ maa_r,
           const float* __restrict__ maa_g) {
    __shared__ float zs[8][NZ];
    const int tid = threadIdx.x;
    const int bt0 = blockIdx.y * 8;
    const int c   = blockIdx.x * 256 + tid;

    for (int idx = tid; idx < 8*NZ; idx += 256)
        zs[idx / NZ][idx % NZ] = g_z[(size_t)(bt0 + idx/NZ)*NZ + (idx % NZ)];
    __syncthreads();

    float acc[5][8];
#pragma unroll
    for (int f = 0; f < 5; f++)
#pragma unroll
        for (int i = 0; i < 8; i++) acc[f][i] = 0.0f;

#pragma unroll
    for (int f = 0; f < 5; f++) {
        for (int d = 0; d < DMIX; d++) {
            float wv = w2[(size_t)(f*DMIX + d)*CQ + c];
#pragma unroll
            for (int i = 0; i < 8; i++) acc[f][i] = fmaf(zs[i][f*DMIX+d], wv, acc[f][i]);
        }
    }
    float mw = maa_w[c], mk = maa_k[c], mv = maa_v[c], mr = maa_r[c], mg = maa_g[c];
#pragma unroll
    for (int i = 0; i < 8; i++) {
        int bt = bt0 + i;
        size_t o = (size_t)bt*CQ + c;
        float h  = hidden[o];
        float sh = ((bt & (TQ-1)) != 0) ? hidden[o - CQ] : 0.0f;
        float xx = sh - h;
        g_xw[o] = h + xx * (mw + acc[0][i]);
        g_xk[o] = h + xx * (mk + acc[1][i]);
        g_xv[o] = h + xx * (mv + acc[2][i]);
        g_xr[o] = h + xx * (mr + acc[3][i]);
        g_xg[o] = h + xx * (mg + acc[4][i]);
    }
}

// ---------------- 6) w = exp(-exp(tmpd@decay_w2 + time_decay)) ----------------
__global__ void __launch_bounds__(256)
decay_final_kernel(const float* __restrict__ w2, const float* __restrict__ tdecay) {
    __shared__ float ts[16][DDEC];
    const int tid = threadIdx.x;
    const int m0  = blockIdx.y * 16;
    const int a   = blockIdx.x * 256 + tid;

    for (int idx = tid; idx < 16*DDEC; idx += 256)
        ts[idx >> 6][idx & 63] = g_tmpd[(size_t)(m0 + (idx >> 6))*DDEC + (idx & 63)];
    __syncthreads();

    float acc[16];
#pragma unroll
    for (int i = 0; i < 16; i++) acc[i] = 0.0f;
    for (int d = 0; d < DDEC; d++) {
        float wv = w2[(size_t)d*AQ + a];
#pragma unroll
        for (int i = 0; i < 16; i++) acc[i] = fmaf(ts[i][d], wv, acc[i]);
    }
    float td = tdecay[a];
#pragma unroll
    for (int i = 0; i < 16; i++)
        g_w[(size_t)(m0+i)*AQ + a] = expf(-expf(acc[i] + td));
}

// ---------------- 7) ruk[b,t,h] = sum_n r*u*k ----------------
__global__ void ruk_kernel(const float* __restrict__ u) {
    int g    = blockIdx.x * 8 + (threadIdx.x >> 5);
    int lane = threadIdx.x & 31;
    int bt = g >> 5;
    int h  = g & 31;
    size_t off = (size_t)bt*AQ + h*HSQ;
    float s = g_r[off+lane]    * u[h*HSQ+lane]    * g_k[off+lane]
            + g_r[off+lane+32] * u[h*HSQ+lane+32] * g_k[off+lane+32];
#pragma unroll
    for (int sh = 16; sh; sh >>= 1) s += __shfl_xor_sync(0xffffffffu, s, sh);
    if (lane == 0) g_ruk[(size_t)bt*HQ + h] = s;
}

// ---------------- 8) WKV sequential scan ----------------
// 64 threads/block, one block per (b,h). Thread m owns state column S[n=0..63][m]
// in registers. Double-buffered smem for (r,k,w); t+1 prefetched into regs while
// computing t; single __syncthreads per step.
__global__ void __launch_bounds__(64)
wkv_kernel() {
    const int h = blockIdx.x, b = blockIdx.y;
    const int m = threadIdx.x;
    __shared__ float4 buf[2][64];

    float S[64];
#pragma unroll
    for (int n = 0; n < 64; n++) S[n] = 0.0f;

    const size_t base = (size_t)b*TQ*AQ + (size_t)h*HSQ;
    size_t off = base;

    float rn = g_r[off + m], kn = g_k[off + m], wn = g_w[off + m];
    float vm = g_v[off + m];
    float ruk = g_ruk[((size_t)b*TQ)*HQ + h];
    buf[0][m] = make_float4(rn, kn, wn, 0.0f);
    __syncthreads();

    for (int t = 0; t < TQ; t++) {
        const int cur = t & 1;
        const size_t offn = off + AQ;
        float vnext = 0.0f, ruknext = 0.0f;
        if (t + 1 < TQ) {
            rn = g_r[offn + m]; kn = g_k[offn + m]; wn = g_w[offn + m];
            vnext = g_v[offn + m];
            ruknext = g_ruk[((size_t)b*TQ + t + 1)*HQ + h];
        }
        float a0 = 0.0f, a1 = 0.0f, a2 = 0.0f, a3 = 0.0f;
#pragma unroll
        for (int n = 0; n < 64; n += 4) {
            float4 q0 = buf[cur][n+0];
            float4 q1 = buf[cur][n+1];
            float4 q2 = buf[cur][n+2];
            float4 q3 = buf[cur][n+3];
            a0 = fmaf(q0.x, S[n+0], a0);  S[n+0] = fmaf(q0.z, S[n+0], q0.y*vm);
            a1 = fmaf(q1.x, S[n+1], a1);  S[n+1] = fmaf(q1.z, S[n+1], q1.y*vm);
            a2 = fmaf(q2.x, S[n+2], a2);  S[n+2] = fmaf(q2.z, S[n+2], q2.y*vm);
            a3 = fmaf(q3.x, S[n+3], a3);  S[n+3] = fmaf(q3.z, S[n+3], q3.y*vm);
        }
        g_att[off + m] = ((a0 + a1) + (a2 + a3)) + vm * ruk;
        if (t + 1 < TQ) {
            buf[cur ^ 1][m] = make_float4(rn, kn, wn, 0.0f);
            vm = vnext; ruk = ruknext;
        }
        __syncthreads();
        off = offn;
    }
}

// ---------------- 9) GroupNorm(per head) * gamma + beta, then * g ----------------
__global__ void gnorm_kernel(const float* __restrict__ gamma, const float* __restrict__ beta) {
    int g    = blockIdx.x * 8 + (threadIdx.x >> 5);
    int lane = threadIdx.x & 31;
    int bt = g >> 5;
    int h  = g & 31;
    size_t off = (size_t)bt*AQ + h*HSQ;
    float x0 = g_att[off+lane], x1 = g_att[off+lane+32];
    float s  = x0 + x1;
    float ss = x0*x0 + x1*x1;
#pragma unroll
    for (int sh = 16; sh; sh >>= 1) {
        s  += __shfl_xor_sync(0xffffffffu, s,  sh);
        ss += __shfl_xor_sync(0xffffffffu, ss, sh);
    }
    float mean = s * (1.0f/64.0f);
    float var  = ss * (1.0f/64.0f) - mean*mean;
    float inv  = rsqrtf(var + EPSG);
    int c0 = h*HSQ + lane, c1 = c0 + 32;
    g_y[off+lane]    = ((x0-mean)*inv*gamma[c0] + beta[c0]) * g_g[off+lane];
    g_y[off+lane+32] = ((x1-mean)*inv*gamma[c1] + beta[c1]) * g_g[off+lane+32];
}

// ---------------- host ----------------
extern "C" void kernel_launch(void* const* d_in, const int* in_sizes, int n_in,
                              void* d_out, int out_size) {
    (void)in_sizes; (void)n_in; (void)out_size;
    const float* hidden  = (const float*)d_in[0];
    const float* maa_x   = (const float*)d_in[1];
    const float* maa_w   = (const float*)d_in[2];
    const float* maa_k   = (const float*)d_in[3];
    const float* maa_v   = (const float*)d_in[4];
    const float* maa_r   = (const float*)d_in[5];
    const float* maa_g   = (const float*)d_in[6];
    const float* maa_w1  = (const float*)d_in[7];
    const float* maa_w2  = (const float*)d_in[8];
    const float* tdecay  = (const float*)d_in[9];
    const float* dec_w1  = (const float*)d_in[10];
    const float* dec_w2  = (const float*)d_in[11];
    const float* u       = (const float*)d_in[12];
    const float* W_r     = (const float*)d_in[13];
    const float* W_k     = (const float*)d_in[14];
    const float* W_v     = (const float*)d_in[15];
    const float* W_g     = (const float*)d_in[16];
    const float* W_o     = (const float*)d_in[17];
    const float* gamma   = (const float*)d_in[18];
    const float* beta    = (const float*)d_in[19];
    float* out = (float*)d_out;

    float *p_xxx, *p_zp, *p_z, *p_xw, *p_xk, *p_xv, *p_xr, *p_xg;
    float *p_r, *p_k, *p_v, *p_g, *p_tp, *p_tmpd, *p_y;
    cudaGetSymbolAddress((void**)&p_xxx,  g_xxx);
    cudaGetSymbolAddress((void**)&p_zp,   g_zp);
    cudaGetSymbolAddress((void**)&p_z,    g_z);
    cudaGetSymbolAddress((void**)&p_xw,   g_xw);
    cudaGetSymbolAddress((void**)&p_xk,   g_xk);
    cudaGetSymbolAddress((void**)&p_xv,   g_xv);
    cudaGetSymbolAddress((void**)&p_xr,   g_xr);
    cudaGetSymbolAddress((void**)&p_xg,   g_xg);
    cudaGetSymbolAddress((void**)&p_r,    g_r);
    cudaGetSymbolAddress((void**)&p_k,    g_k);
    cudaGetSymbolAddress((void**)&p_v,    g_v);
    cudaGetSymbolAddress((void**)&p_g,    g_g);
    cudaGetSymbolAddress((void**)&p_tp,   g_tp);
    cudaGetSymbolAddress((void**)&p_tmpd, g_tmpd);
    cudaGetSymbolAddress((void**)&p_y,    g_y);

    // 1) xxx
    prep_xxx_kernel<<<(MQ*CQ)/256, 256>>>(hidden, maa_x);
    // 2) z = tanh(xxx @ time_maa_w1)  via split-K slabs + fused-tanh reduce
    sgemm_splitk_kernel<<<dim3(2, 32, NSLAB), 256>>>(p_xxx, maa_w1, p_zp, MQ, NZ, CQ);
    reduce8_tanh_kernel<<<(MQ*NZ + 255)/256, 256>>>(p_zp, p_z, MQ*NZ);
    // 3) mix -> xw,xk,xv,xr,xg
    mix_kernel<<<dim3(CQ/256, MQ/8), 256>>>(hidden, maa_w2, maa_w, maa_k, maa_v, maa_r, maa_g);
    // 5) decay low-rank stage 1 (fp32 exact, split-K)
    sgemm_splitk_kernel<<<dim3(1, 32, NSLAB), 256>>>(p_xw, dec_w1, p_tp, MQ, DDEC, CQ);
    reduce8_tanh_kernel<<<(MQ*DDEC + 255)/256, 256>>>(p_tp, p_tmpd, MQ*DDEC);
    // 6) w = exp(-exp(tmpd @ decay_w2 + time_decay))
    decay_final_kernel<<<dim3(AQ/256, MQ/16), 256>>>(dec_w2, tdecay);
    // 4) big NT GEMMs on tensor cores (bf16 3-term)
    gemm_bf16_nt<EPI_NONE><<<dim3(AQ/128, MQ/128), 256>>>(p_xr, W_r, p_r, MQ, AQ, CQ);
    gemm_bf16_nt<EPI_NONE><<<dim3(AQ/128, MQ/128), 256>>>(p_xk, W_k, p_k, MQ, AQ, CQ);
    gemm_bf16_nt<EPI_NONE><<<dim3(AQ/128, MQ/128), 256>>>(p_xv, W_v, p_v, MQ, AQ, CQ);
    gemm_bf16_nt<EPI_SILU><<<dim3(AQ/128, MQ/128), 256>>>(p_xg, W_g, p_g, MQ, AQ, CQ);
    // 7) ruk
    ruk_kernel<<<(MQ*HQ)/8, 256>>>(u);
    // 8) WKV scan
    wkv_kernel<<<dim3(HQ, BQ), 64>>>();
    // 9) GroupNorm + gate
    gnorm_kernel<<<(MQ*HQ)/8, 256>>>(gamma, beta);
    // 10) out = y @ W_o^T
    gemm_bf16_nt<EPI_NONE><<<dim3(CQ/128, MQ/128), 256>>>(p_y, W_o, out, MQ, CQ, AQ);
}